// round 2
// baseline (speedup 1.0000x reference)
#include <cuda_runtime.h>
#include <cuda_bf16.h>
#include <cstdint>

#define B_   128
#define S_   512
#define E_   300
#define KP   320     // padded K for GEMM
#define H_   128
#define G4   512     // 4*H
#define T_   12
#define SOS_ 3
#define EOS_ 4
#define NEGV (-10000.0f)

// ---------------- scratch (static device allocations) ----------------
__device__ __align__(16) __nv_bfloat16 g_emb[(size_t)B_*S_*KP];   // [65536][320]
__device__ __align__(16) __nv_bfloat16 g_wcat[1024*KP];           // [1024][320]  rows: 0..511 Wih_f, 512..1023 Wih_b
__device__ __align__(16) __nv_bfloat16 g_whh[2*G4*H_];            // [2][512][128]
__device__ float g_bias[1024];
__device__ float g_pre[(size_t)2*B_*S_*G4];                       // [2][128][512][512]
__device__ __align__(16) float g_hcat[(size_t)B_*S_*2*H_];        // [65536][256]  (hf | hb)
__device__ float g_y[(size_t)B_*S_*T_];                           // [65536][12]

// ---------------- helpers ----------------
__device__ __forceinline__ float tanhapx(float x) {
    float r; asm("tanh.approx.f32 %0, %1;" : "=f"(r) : "f"(x)); return r;
}
__device__ __forceinline__ float sigf(float x) {
    return 0.5f + 0.5f * tanhapx(0.5f * x);
}

// ---------------- K1: embedding gather -> bf16, K-padded ----------------
__global__ void k_prep_emb(const int* __restrict__ x, const float* __restrict__ embed) {
    int row = blockIdx.x;        // 0..65535  (= b*512 + s)
    int k   = threadIdx.x;       // 0..319
    int xv = x[row];
    float v = (k < E_) ? embed[(size_t)xv * E_ + k] : 0.0f;
    g_emb[(size_t)row * KP + k] = __float2bfloat16(v);
}

// ---------------- K1b: weight packing ----------------
__global__ void k_prep_w(const float* __restrict__ Wih_f, const float* __restrict__ Whh_f,
                         const float* __restrict__ b_f,
                         const float* __restrict__ Wih_b, const float* __restrict__ Whh_b,
                         const float* __restrict__ b_b) {
    int idx = blockIdx.x * blockDim.x + threadIdx.x;
    const int NW = 1024 * KP;
    const int NH = 2 * G4 * H_;
    if (idx < NW) {
        int r = idx / KP, k = idx % KP;
        float v = 0.0f;
        if (k < E_) v = (r < G4) ? Wih_f[r * E_ + k] : Wih_b[(r - G4) * E_ + k];
        g_wcat[idx] = __float2bfloat16(v);
    } else if (idx < NW + NH) {
        int i = idx - NW;
        int d = i / (G4 * H_);
        int rem = i % (G4 * H_);
        float v = d ? Whh_b[rem] : Whh_f[rem];
        g_whh[i] = __float2bfloat16(v);
    } else if (idx < NW + NH + 1024) {
        int n = idx - NW - NH;
        g_bias[n] = (n < G4) ? b_f[n] : b_b[n - G4];
    }
}

// ---------------- K2: input GEMM (bf16 mma.sync, fp32 accum) ----------------
// C[m,n] = sum_k EMB[m,k] * WCAT[n,k];  M=65536, N=1024, K=320
#define BM 128
#define BN 64
#define BK 32
#define SA 40   // padded smem stride (bf16 units)

__global__ __launch_bounds__(256) void k_gemm_in() {
    __shared__ __align__(16) __nv_bfloat16 As[BM * SA];
    __shared__ __align__(16) __nv_bfloat16 Bs[BN * SA];
    const int m0 = blockIdx.y * BM;
    const int n0 = blockIdx.x * BN;
    const int tid = threadIdx.x;
    const int warp = tid >> 5, lane = tid & 31;
    const int wm = warp >> 1, wn = warp & 1;     // 4 x 2 warp grid, warp tile 32x32

    float acc[2][4][4];
    #pragma unroll
    for (int a = 0; a < 2; a++)
        #pragma unroll
        for (int b = 0; b < 4; b++)
            #pragma unroll
            for (int c = 0; c < 4; c++) acc[a][b][c] = 0.0f;

    const int lr = lane >> 2, lc = (lane & 3) * 2;

    for (int kt = 0; kt < KP; kt += BK) {
        {   // load A tile 128x32 (2 uint4/thread) and B tile 64x32 (1 uint4/thread)
            int r = tid >> 2, seg = tid & 3;
            *(uint4*)&As[r * SA + seg * 8] =
                *(const uint4*)&g_emb[(size_t)(m0 + r) * KP + kt + seg * 8];
            *(uint4*)&As[(r + 64) * SA + seg * 8] =
                *(const uint4*)&g_emb[(size_t)(m0 + r + 64) * KP + kt + seg * 8];
            *(uint4*)&Bs[r * SA + seg * 8] =
                *(const uint4*)&g_wcat[(size_t)(n0 + r) * KP + kt + seg * 8];
        }
        __syncthreads();
        #pragma unroll
        for (int ks = 0; ks < 2; ks++) {
            const int kb = ks * 16;
            uint32_t bfr[4][2];
            #pragma unroll
            for (int ni = 0; ni < 4; ni++) {
                int nrow = wn * 32 + ni * 8 + lr;
                bfr[ni][0] = *(const uint32_t*)&Bs[nrow * SA + kb + lc];
                bfr[ni][1] = *(const uint32_t*)&Bs[nrow * SA + kb + lc + 8];
            }
            #pragma unroll
            for (int mi = 0; mi < 2; mi++) {
                int mrow = wm * 32 + mi * 16;
                uint32_t a0 = *(const uint32_t*)&As[(mrow + lr    ) * SA + kb + lc];
                uint32_t a1 = *(const uint32_t*)&As[(mrow + lr + 8) * SA + kb + lc];
                uint32_t a2 = *(const uint32_t*)&As[(mrow + lr    ) * SA + kb + lc + 8];
                uint32_t a3 = *(const uint32_t*)&As[(mrow + lr + 8) * SA + kb + lc + 8];
                #pragma unroll
                for (int ni = 0; ni < 4; ni++) {
                    asm volatile(
                        "mma.sync.aligned.m16n8k16.row.col.f32.bf16.bf16.f32 "
                        "{%0,%1,%2,%3}, {%4,%5,%6,%7}, {%8,%9}, {%0,%1,%2,%3};\n"
                        : "+f"(acc[mi][ni][0]), "+f"(acc[mi][ni][1]),
                          "+f"(acc[mi][ni][2]), "+f"(acc[mi][ni][3])
                        : "r"(a0), "r"(a1), "r"(a2), "r"(a3),
                          "r"(bfr[ni][0]), "r"(bfr[ni][1]));
                }
            }
        }
        __syncthreads();
    }
    // epilogue: add bias, scatter to PRE[d][b][s][j]
    #pragma unroll
    for (int mi = 0; mi < 2; mi++) {
        #pragma unroll
        for (int ni = 0; ni < 4; ni++) {
            int m = m0 + wm * 32 + mi * 16 + lr;
            int n = n0 + wn * 32 + ni * 8 + lc;
            int d = n >> 9, j = n & 511;
            float bias0 = g_bias[n], bias1 = g_bias[n + 1];
            {
                int bb = m >> 9, ss = m & 511;
                size_t base = (((size_t)(d * B_ + bb) * S_ + ss) * G4 + j);
                *(float2*)&g_pre[base] = make_float2(acc[mi][ni][0] + bias0,
                                                     acc[mi][ni][1] + bias1);
            }
            {
                int m2 = m + 8;
                int bb = m2 >> 9, ss = m2 & 511;
                size_t base = (((size_t)(d * B_ + bb) * S_ + ss) * G4 + j);
                *(float2*)&g_pre[base] = make_float2(acc[mi][ni][2] + bias0,
                                                     acc[mi][ni][3] + bias1);
            }
        }
    }
}

// ---------------- K3: recurrence ----------------
// grid = 128 blocks: block = (dir, batch pair). 512 threads, thread j owns gate row j.
// Whh row (128 bf16) lives in 64 registers; fp32 accumulate; h via smem broadcast.
__global__ __launch_bounds__(512, 1) void k_lstm() {
    __shared__ __align__(16) float h_sm[2][H_];
    __shared__ float g_sm[2][G4];

    const int d  = blockIdx.x >> 6;
    const int bp = blockIdx.x & 63;
    const int b0 = bp * 2, b1 = b0 + 1;
    const int j  = threadIdx.x;

    uint4 w[16];
    {
        const uint4* src = (const uint4*)&g_whh[((size_t)d * G4 + j) * H_];
        #pragma unroll
        for (int t = 0; t < 16; t++) w[t] = src[t];
    }
    if (j < 2 * H_) h_sm[j >> 7][j & 127] = 0.0f;
    float c_st = 0.0f;
    __syncthreads();

    const float* preb0 = &g_pre[((size_t)(d * B_ + b0) * S_) * G4];
    const float* preb1 = &g_pre[((size_t)(d * B_ + b1) * S_) * G4];

    for (int s = 0; s < S_; s++) {
        const int se = d ? (S_ - 1 - s) : s;
        // pre-activation loads (independent of h -> hidden under the k-loop)
        float p0 = preb0[(size_t)se * G4 + j];
        float p1 = preb1[(size_t)se * G4 + j];

        float a0e = 0.f, a0o = 0.f, a1e = 0.f, a1o = 0.f;
        #pragma unroll
        for (int t = 0; t < 16; t++) {
            float4 ha = *(const float4*)&h_sm[0][t * 8];
            float4 hb = *(const float4*)&h_sm[0][t * 8 + 4];
            float4 ca = *(const float4*)&h_sm[1][t * 8];
            float4 cb = *(const float4*)&h_sm[1][t * 8 + 4];
            uint32_t u;
            float w0, w1;
            u = w[t].x;
            w0 = __uint_as_float(u << 16); w1 = __uint_as_float(u & 0xffff0000u);
            a0e = fmaf(w0, ha.x, a0e); a0o = fmaf(w1, ha.y, a0o);
            a1e = fmaf(w0, ca.x, a1e); a1o = fmaf(w1, ca.y, a1o);
            u = w[t].y;
            w0 = __uint_as_float(u << 16); w1 = __uint_as_float(u & 0xffff0000u);
            a0e = fmaf(w0, ha.z, a0e); a0o = fmaf(w1, ha.w, a0o);
            a1e = fmaf(w0, ca.z, a1e); a1o = fmaf(w1, ca.w, a1o);
            u = w[t].z;
            w0 = __uint_as_float(u << 16); w1 = __uint_as_float(u & 0xffff0000u);
            a0e = fmaf(w0, hb.x, a0e); a0o = fmaf(w1, hb.y, a0o);
            a1e = fmaf(w0, cb.x, a1e); a1o = fmaf(w1, cb.y, a1o);
            u = w[t].w;
            w0 = __uint_as_float(u << 16); w1 = __uint_as_float(u & 0xffff0000u);
            a0e = fmaf(w0, hb.z, a0e); a0o = fmaf(w1, hb.w, a0o);
            a1e = fmaf(w0, cb.z, a1e); a1o = fmaf(w1, cb.w, a1o);
        }
        g_sm[0][j] = a0e + a0o + p0;
        g_sm[1][j] = a1e + a1o + p1;
        __syncthreads();
        if (j < 256) {
            const int ch = j >> 7, m = j & 127;
            float gi = g_sm[ch][m];
            float gf = g_sm[ch][H_ + m];
            float gg = g_sm[ch][2 * H_ + m];
            float go = g_sm[ch][3 * H_ + m];
            c_st = sigf(gf) * c_st + sigf(gi) * tanhapx(gg);
            float h = sigf(go) * tanhapx(c_st);
            h_sm[ch][m] = h;
            const int bb = ch ? b1 : b0;
            g_hcat[((size_t)bb * S_ + se) * (2 * H_) + d * H_ + m] = h;
        }
        __syncthreads();
    }
}

// ---------------- K4: output linear y = hcat @ Wout^T + bout ----------------
__global__ void k_out(const float* __restrict__ Wout, const float* __restrict__ bout) {
    const int lr = threadIdx.x >> 4;
    const int t  = threadIdx.x & 15;
    const int row = blockIdx.x * 16 + lr;
    if (t >= T_) return;
    float acc = bout[t];
    const float4* hv = (const float4*)&g_hcat[(size_t)row * 256];
    const float4* wv = (const float4*)&Wout[t * 256];
    #pragma unroll 8
    for (int q = 0; q < 64; q++) {
        float4 h4 = hv[q], w4 = wv[q];
        acc += h4.x * w4.x + h4.y * w4.y + h4.z * w4.z + h4.w * w4.w;
    }
    g_y[(size_t)row * T_ + t] = acc;
}

// ---------------- K5: CRF forward (Z) + gold score, out = Z - gold ----------------
__global__ void k_crf(const int* __restrict__ y0, const float* __restrict__ trans,
                      float* __restrict__ out) {
    __shared__ float tsm[T_ * T_];
    const int b = blockIdx.x;
    const int lane = threadIdx.x;
    for (int i = lane; i < T_ * T_; i += 32) tsm[i] = trans[i];
    __syncwarp();

    float trow[T_];
    const int irow = (lane < T_) ? lane : 0;
    #pragma unroll
    for (int jj = 0; jj < T_; jj++) trow[jj] = tsm[irow * T_ + jj];

    float score = (lane == SOS_) ? 0.0f : NEGV;
    const float* gyb = &g_y[(size_t)b * S_ * T_];

    for (int s = 0; s < S_; s++) {
        float yv = (lane < T_) ? gyb[s * T_ + lane] : 0.0f;
        float v[T_];
        float mx = -1e30f;
        #pragma unroll
        for (int jj = 0; jj < T_; jj++) {
            float sj = __shfl_sync(0xffffffffu, score, jj);
            v[jj] = sj + trow[jj];
            mx = fmaxf(mx, v[jj]);
        }
        float sum = 0.0f;
        #pragma unroll
        for (int jj = 0; jj < T_; jj++) sum += __expf(v[jj] - mx);
        score = mx + __logf(sum) + yv;
    }
    // Z = lse_i(score_i + trans[EOS][i])
    float vz = (lane < T_) ? score + tsm[EOS_ * T_ + lane] : -1e30f;
    float mz = vz;
    #pragma unroll
    for (int o = 16; o; o >>= 1) mz = fmaxf(mz, __shfl_xor_sync(0xffffffffu, mz, o));
    float ez = (lane < T_) ? __expf(vz - mz) : 0.0f;
    #pragma unroll
    for (int o = 16; o; o >>= 1) ez += __shfl_xor_sync(0xffffffffu, ez, o);
    float Z = mz + __logf(ez);

    // gold path
    const int* yb = &y0[b * S_];
    float g = 0.0f;
    for (int s = lane; s < S_; s += 32) {
        int cur = yb[s];
        int prev = s ? yb[s - 1] : SOS_;
        g += gyb[s * T_ + cur] + tsm[cur * T_ + prev];
    }
    #pragma unroll
    for (int o = 16; o; o >>= 1) g += __shfl_xor_sync(0xffffffffu, g, o);
    if (lane == 0) {
        g += tsm[EOS_ * T_ + yb[S_ - 1]];
        out[b] = Z - g;
    }
}

// ---------------- launcher ----------------
extern "C" void kernel_launch(void* const* d_in, const int* in_sizes, int n_in,
                              void* d_out, int out_size) {
    const int*   x     = (const int*)d_in[0];
    const int*   y0    = (const int*)d_in[1];
    const float* embed = (const float*)d_in[2];
    const float* Wih_f = (const float*)d_in[3];
    const float* Whh_f = (const float*)d_in[4];
    const float* b_f   = (const float*)d_in[5];
    const float* Wih_b = (const float*)d_in[6];
    const float* Whh_b = (const float*)d_in[7];
    const float* b_b   = (const float*)d_in[8];
    const float* Wout  = (const float*)d_in[9];
    const float* bout  = (const float*)d_in[10];
    const float* trans = (const float*)d_in[11];
    float* out = (float*)d_out;

    k_prep_emb<<<B_ * S_, KP>>>(x, embed);

    const int prep_total = 1024 * KP + 2 * G4 * H_ + 1024;
    k_prep_w<<<(prep_total + 255) / 256, 256>>>(Wih_f, Whh_f, b_f, Wih_b, Whh_b, b_b);

    dim3 gg(1024 / BN, (B_ * S_) / BM);   // (16, 512) — n inner for A-tile L2 reuse
    k_gemm_in<<<gg, 256>>>();

    k_lstm<<<128, 512>>>();

    k_out<<<(B_ * S_) / 16, 256>>>(Wout, bout);

    k_crf<<<B_, 32>>>(y0, trans, out);
}

// round 3
// speedup vs baseline: 2.0355x; 2.0355x over previous
#include <cuda_runtime.h>
#include <cuda_bf16.h>
#include <cstdint>

#define B_   128
#define S_   512
#define E_   300
#define KP   320     // padded K for GEMM
#define H_   128
#define G4   512     // 4*H
#define T_   12
#define SOS_ 3
#define EOS_ 4
#define NEGV (-10000.0f)

// ---------------- scratch (static device allocations) ----------------
__device__ __align__(16) __nv_bfloat16 g_emb[(size_t)B_*S_*KP];   // [65536][320]
__device__ __align__(16) __nv_bfloat16 g_wcat[1024*KP];           // [1024][320]
__device__ __align__(16) __nv_bfloat16 g_whh[2*G4*H_];            // [2][512][128]
__device__ float g_bias[1024];
__device__ float g_pre[(size_t)2*B_*S_*G4];                       // [2][128][512][512]
__device__ __align__(16) float g_hcat[(size_t)B_*S_*2*H_];        // [65536][256]
__device__ float g_y[(size_t)B_*S_*T_];                           // [65536][12]

// ---------------- helpers ----------------
__device__ __forceinline__ float tanhapx(float x) {
    float r; asm("tanh.approx.f32 %0, %1;" : "=f"(r) : "f"(x)); return r;
}
__device__ __forceinline__ float sigf(float x) {
    return 0.5f + 0.5f * tanhapx(0.5f * x);
}
__device__ __forceinline__ void cp16(void* smem, const void* gmem) {
    uint32_t s = (uint32_t)__cvta_generic_to_shared(smem);
    asm volatile("cp.async.cg.shared.global [%0], [%1], 16;\n" :: "r"(s), "l"(gmem) : "memory");
}
__device__ __forceinline__ void cp_commit() {
    asm volatile("cp.async.commit_group;\n" ::: "memory");
}
template<int N> __device__ __forceinline__ void cp_wait() {
    asm volatile("cp.async.wait_group %0;\n" :: "n"(N) : "memory");
}

// ---------------- K1: embedding gather -> bf16, K-padded ----------------
__global__ void k_prep_emb(const int* __restrict__ x, const float* __restrict__ embed) {
    int row = blockIdx.x;
    int k   = threadIdx.x;
    int xv = x[row];
    float v = (k < E_) ? embed[(size_t)xv * E_ + k] : 0.0f;
    g_emb[(size_t)row * KP + k] = __float2bfloat16(v);
}

// ---------------- K1b: weight packing ----------------
__global__ void k_prep_w(const float* __restrict__ Wih_f, const float* __restrict__ Whh_f,
                         const float* __restrict__ b_f,
                         const float* __restrict__ Wih_b, const float* __restrict__ Whh_b,
                         const float* __restrict__ b_b) {
    int idx = blockIdx.x * blockDim.x + threadIdx.x;
    const int NW = 1024 * KP;
    const int NH = 2 * G4 * H_;
    if (idx < NW) {
        int r = idx / KP, k = idx % KP;
        float v = 0.0f;
        if (k < E_) v = (r < G4) ? Wih_f[r * E_ + k] : Wih_b[(r - G4) * E_ + k];
        g_wcat[idx] = __float2bfloat16(v);
    } else if (idx < NW + NH) {
        int i = idx - NW;
        int d = i / (G4 * H_);
        int rem = i % (G4 * H_);
        float v = d ? Whh_b[rem] : Whh_f[rem];
        g_whh[i] = __float2bfloat16(v);
    } else if (idx < NW + NH + 1024) {
        int n = idx - NW - NH;
        g_bias[n] = (n < G4) ? b_f[n] : b_b[n - G4];
    }
}

// ---------------- K2: input GEMM (bf16 mma.sync, fp32 accum, cp.async 2-stage) ----------------
#define BM 128
#define BN 64
#define BK 32
#define SA 40
#define KITERS (KP / BK)   // 10

__global__ __launch_bounds__(256) void k_gemm_in() {
    __shared__ __align__(16) __nv_bfloat16 As[2][BM * SA];
    __shared__ __align__(16) __nv_bfloat16 Bs[2][BN * SA];
    const int m0 = blockIdx.y * BM;
    const int n0 = blockIdx.x * BN;
    const int tid = threadIdx.x;
    const int warp = tid >> 5, lane = tid & 31;
    const int wm = warp >> 1, wn = warp & 1;

    float acc[2][4][4];
    #pragma unroll
    for (int a = 0; a < 2; a++)
        #pragma unroll
        for (int b = 0; b < 4; b++)
            #pragma unroll
            for (int c = 0; c < 4; c++) acc[a][b][c] = 0.0f;

    const int lr = lane >> 2, lc = (lane & 3) * 2;
    const int ldr = tid >> 2, seg = tid & 3;

    // prologue: stage 0
    cp16(&As[0][ldr * SA + seg * 8],        &g_emb[(size_t)(m0 + ldr) * KP + seg * 8]);
    cp16(&As[0][(ldr + 64) * SA + seg * 8], &g_emb[(size_t)(m0 + ldr + 64) * KP + seg * 8]);
    cp16(&Bs[0][ldr * SA + seg * 8],        &g_wcat[(size_t)(n0 + ldr) * KP + seg * 8]);
    cp_commit();

    for (int it = 0; it < KITERS; it++) {
        if (it + 1 < KITERS) {
            const int kt = (it + 1) * BK;
            const int st = (it + 1) & 1;
            cp16(&As[st][ldr * SA + seg * 8],        &g_emb[(size_t)(m0 + ldr) * KP + kt + seg * 8]);
            cp16(&As[st][(ldr + 64) * SA + seg * 8], &g_emb[(size_t)(m0 + ldr + 64) * KP + kt + seg * 8]);
            cp16(&Bs[st][ldr * SA + seg * 8],        &g_wcat[(size_t)(n0 + ldr) * KP + kt + seg * 8]);
            cp_commit();
            cp_wait<1>();
        } else {
            cp_wait<0>();
        }
        __syncthreads();
        const int st = it & 1;
        #pragma unroll
        for (int ks = 0; ks < 2; ks++) {
            const int kb = ks * 16;
            uint32_t bfr[4][2];
            #pragma unroll
            for (int ni = 0; ni < 4; ni++) {
                int nrow = wn * 32 + ni * 8 + lr;
                bfr[ni][0] = *(const uint32_t*)&Bs[st][nrow * SA + kb + lc];
                bfr[ni][1] = *(const uint32_t*)&Bs[st][nrow * SA + kb + lc + 8];
            }
            #pragma unroll
            for (int mi = 0; mi < 2; mi++) {
                int mrow = wm * 32 + mi * 16;
                uint32_t a0 = *(const uint32_t*)&As[st][(mrow + lr    ) * SA + kb + lc];
                uint32_t a1 = *(const uint32_t*)&As[st][(mrow + lr + 8) * SA + kb + lc];
                uint32_t a2 = *(const uint32_t*)&As[st][(mrow + lr    ) * SA + kb + lc + 8];
                uint32_t a3 = *(const uint32_t*)&As[st][(mrow + lr + 8) * SA + kb + lc + 8];
                #pragma unroll
                for (int ni = 0; ni < 4; ni++) {
                    asm volatile(
                        "mma.sync.aligned.m16n8k16.row.col.f32.bf16.bf16.f32 "
                        "{%0,%1,%2,%3}, {%4,%5,%6,%7}, {%8,%9}, {%0,%1,%2,%3};\n"
                        : "+f"(acc[mi][ni][0]), "+f"(acc[mi][ni][1]),
                          "+f"(acc[mi][ni][2]), "+f"(acc[mi][ni][3])
                        : "r"(a0), "r"(a1), "r"(a2), "r"(a3),
                          "r"(bfr[ni][0]), "r"(bfr[ni][1]));
                }
            }
        }
        __syncthreads();
    }
    // epilogue: add bias, scatter to PRE[d][b][s][j]
    #pragma unroll
    for (int mi = 0; mi < 2; mi++) {
        #pragma unroll
        for (int ni = 0; ni < 4; ni++) {
            int m = m0 + wm * 32 + mi * 16 + lr;
            int n = n0 + wn * 32 + ni * 8 + lc;
            int d = n >> 9, j = n & 511;
            float bias0 = g_bias[n], bias1 = g_bias[n + 1];
            {
                int bb = m >> 9, ss = m & 511;
                size_t base = (((size_t)(d * B_ + bb) * S_ + ss) * G4 + j);
                *(float2*)&g_pre[base] = make_float2(acc[mi][ni][0] + bias0,
                                                     acc[mi][ni][1] + bias1);
            }
            {
                int m2 = m + 8;
                int bb = m2 >> 9, ss = m2 & 511;
                size_t base = (((size_t)(d * B_ + bb) * S_ + ss) * G4 + j);
                *(float2*)&g_pre[base] = make_float2(acc[mi][ni][2] + bias0,
                                                     acc[mi][ni][3] + bias1);
            }
        }
    }
}

// ---------------- K3: tensor-core recurrence ----------------
// 32 blocks = (dir, 8-batch group). 512 threads = 16 warps.
// Warp w: M=16 (8 real batches), its 4 n8-tiles are gates {w*8 + ni*128}.
// => each thread holds i,f,g,o for its 2 cells in registers; no gate exchange.
// h double-buffered in smem bf16; 1 barrier per step.
#define HS 136   // h_sm row stride in bf16 (272B -> conflict-free ldmatrix)

__global__ __launch_bounds__(512, 1) void k_lstm() {
    __shared__ __align__(16) __nv_bfloat16 h_sm[2][16][HS];

    const int d   = blockIdx.x >> 4;
    const int bg  = blockIdx.x & 15;
    const int b0  = bg * 8;
    const int tid = threadIdx.x;
    const int w = tid >> 5, l = tid & 31;
    const int r = l >> 2, cpair = (l & 3) * 2;

    // preload B fragments (Whh) once: 64 regs
    uint32_t Bf[4][8][2];
    {
        #pragma unroll
        for (int ni = 0; ni < 4; ni++) {
            const int n = w * 8 + ni * 128 + (l >> 2);
            const __nv_bfloat16* src = &g_whh[((size_t)d * G4 + n) * H_ + (l & 3) * 2];
            #pragma unroll
            for (int tk = 0; tk < 8; tk++) {
                Bf[ni][tk][0] = *(const uint32_t*)&src[tk * 16];
                Bf[ni][tk][1] = *(const uint32_t*)&src[tk * 16 + 8];
            }
        }
    }
    // zero both h buffers (rows 8-15 stay zero forever = M padding)
    for (int i = tid; i < 2 * 16 * HS; i += 512)
        ((__nv_bfloat16*)h_sm)[i] = __float2bfloat16(0.0f);

    const int b  = b0 + r;
    const int m0 = w * 8 + cpair;
    const float* preb = &g_pre[((size_t)(d * B_ + b) * S_) * G4 + m0];
    float* hout = &g_hcat[((size_t)b * S_) * 256 + d * H_ + m0];

    float2 pf[4];
    {
        const int se0 = d ? (S_ - 1) : 0;
        #pragma unroll
        for (int ni = 0; ni < 4; ni++)
            pf[ni] = *(const float2*)&preb[(size_t)se0 * G4 + ni * 128];
    }
    float cA = 0.0f, cB = 0.0f;

    const uint32_t abase0 =
        (uint32_t)__cvta_generic_to_shared(&h_sm[0][l & 15][(l >> 4) * 8]);

    __syncthreads();

    int buf = 0;
    for (int s = 0; s < S_; s++) {
        const int se = d ? (S_ - 1 - s) : s;
        const int sn = d ? (se > 0 ? se - 1 : 0) : (se < S_ - 1 ? se + 1 : S_ - 1);

        // prefetch next step's pre-activations (independent of recurrence)
        float2 npf[4];
        #pragma unroll
        for (int ni = 0; ni < 4; ni++)
            npf[ni] = *(const float2*)&preb[(size_t)sn * G4 + ni * 128];

        // acc init = current pre-activations (bias already folded in)
        float acc[4][4];
        #pragma unroll
        for (int ni = 0; ni < 4; ni++) {
            acc[ni][0] = pf[ni].x; acc[ni][1] = pf[ni].y;
            acc[ni][2] = 0.0f;     acc[ni][3] = 0.0f;
        }

        const uint32_t abase = abase0 + (uint32_t)buf * (16 * HS * 2);
        #pragma unroll
        for (int tk = 0; tk < 8; tk++) {
            uint32_t a0, a1, a2, a3;
            asm volatile("ldmatrix.sync.aligned.m8n8.x4.shared.b16 {%0,%1,%2,%3}, [%4];\n"
                         : "=r"(a0), "=r"(a1), "=r"(a2), "=r"(a3)
                         : "r"(abase + tk * 32));
            #pragma unroll
            for (int ni = 0; ni < 4; ni++) {
                asm volatile(
                    "mma.sync.aligned.m16n8k16.row.col.f32.bf16.bf16.f32 "
                    "{%0,%1,%2,%3}, {%4,%5,%6,%7}, {%8,%9}, {%0,%1,%2,%3};\n"
                    : "+f"(acc[ni][0]), "+f"(acc[ni][1]),
                      "+f"(acc[ni][2]), "+f"(acc[ni][3])
                    : "r"(a0), "r"(a1), "r"(a2), "r"(a3),
                      "r"(Bf[ni][tk][0]), "r"(Bf[ni][tk][1]));
            }
        }

        // gates: ni 0=i, 1=f, 2=g, 3=o ; 2 cells (m0, m0+1), batch b
        cA = sigf(acc[1][0]) * cA + sigf(acc[0][0]) * tanhapx(acc[2][0]);
        cB = sigf(acc[1][1]) * cB + sigf(acc[0][1]) * tanhapx(acc[2][1]);
        float hA = sigf(acc[3][0]) * tanhapx(cA);
        float hB = sigf(acc[3][1]) * tanhapx(cB);

        *(__nv_bfloat162*)&h_sm[buf ^ 1][r][m0] = __floats2bfloat162_rn(hA, hB);
        *(float2*)&hout[(size_t)se * 256] = make_float2(hA, hB);

        #pragma unroll
        for (int ni = 0; ni < 4; ni++) pf[ni] = npf[ni];
        __syncthreads();
        buf ^= 1;
    }
}

// ---------------- K4: output linear ----------------
__global__ void k_out(const float* __restrict__ Wout, const float* __restrict__ bout) {
    const int lr = threadIdx.x >> 4;
    const int t  = threadIdx.x & 15;
    const int row = blockIdx.x * 16 + lr;
    if (t >= T_) return;
    float acc = bout[t];
    const float4* hv = (const float4*)&g_hcat[(size_t)row * 256];
    const float4* wv = (const float4*)&Wout[t * 256];
    #pragma unroll 8
    for (int q = 0; q < 64; q++) {
        float4 h4 = hv[q], w4 = wv[q];
        acc += h4.x * w4.x + h4.y * w4.y + h4.z * w4.z + h4.w * w4.w;
    }
    g_y[(size_t)row * T_ + t] = acc;
}

// ---------------- K5: CRF forward + gold ----------------
__global__ void k_crf(const int* __restrict__ y0, const float* __restrict__ trans,
                      float* __restrict__ out) {
    __shared__ float tsm[T_ * T_];
    const int b = blockIdx.x;
    const int lane = threadIdx.x;
    for (int i = lane; i < T_ * T_; i += 32) tsm[i] = trans[i];
    __syncwarp();

    float trow[T_];
    const int irow = (lane < T_) ? lane : 0;
    #pragma unroll
    for (int jj = 0; jj < T_; jj++) trow[jj] = tsm[irow * T_ + jj];

    float score = (lane == SOS_) ? 0.0f : NEGV;
    const float* gyb = &g_y[(size_t)b * S_ * T_];

    for (int s = 0; s < S_; s++) {
        float yv = (lane < T_) ? gyb[s * T_ + lane] : 0.0f;
        float v[T_];
        float mx = -1e30f;
        #pragma unroll
        for (int jj = 0; jj < T_; jj++) {
            float sj = __shfl_sync(0xffffffffu, score, jj);
            v[jj] = sj + trow[jj];
            mx = fmaxf(mx, v[jj]);
        }
        float sum = 0.0f;
        #pragma unroll
        for (int jj = 0; jj < T_; jj++) sum += __expf(v[jj] - mx);
        score = mx + __logf(sum) + yv;
    }
    float vz = (lane < T_) ? score + tsm[EOS_ * T_ + lane] : -1e30f;
    float mz = vz;
    #pragma unroll
    for (int o = 16; o; o >>= 1) mz = fmaxf(mz, __shfl_xor_sync(0xffffffffu, mz, o));
    float ez = (lane < T_) ? __expf(vz - mz) : 0.0f;
    #pragma unroll
    for (int o = 16; o; o >>= 1) ez += __shfl_xor_sync(0xffffffffu, ez, o);
    float Z = mz + __logf(ez);

    const int* yb = &y0[b * S_];
    float g = 0.0f;
    for (int s = lane; s < S_; s += 32) {
        int cur = yb[s];
        int prev = s ? yb[s - 1] : SOS_;
        g += gyb[s * T_ + cur] + tsm[cur * T_ + prev];
    }
    #pragma unroll
    for (int o = 16; o; o >>= 1) g += __shfl_xor_sync(0xffffffffu, g, o);
    if (lane == 0) {
        g += tsm[EOS_ * T_ + yb[S_ - 1]];
        out[b] = Z - g;
    }
}

// ---------------- launcher ----------------
extern "C" void kernel_launch(void* const* d_in, const int* in_sizes, int n_in,
                              void* d_out, int out_size) {
    const int*   x     = (const int*)d_in[0];
    const int*   y0    = (const int*)d_in[1];
    const float* embed = (const float*)d_in[2];
    const float* Wih_f = (const float*)d_in[3];
    const float* Whh_f = (const float*)d_in[4];
    const float* b_f   = (const float*)d_in[5];
    const float* Wih_b = (const float*)d_in[6];
    const float* Whh_b = (const float*)d_in[7];
    const float* b_b   = (const float*)d_in[8];
    const float* Wout  = (const float*)d_in[9];
    const float* bout  = (const float*)d_in[10];
    const float* trans = (const float*)d_in[11];
    float* out = (float*)d_out;

    k_prep_emb<<<B_ * S_, KP>>>(x, embed);

    const int prep_total = 1024 * KP + 2 * G4 * H_ + 1024;
    k_prep_w<<<(prep_total + 255) / 256, 256>>>(Wih_f, Whh_f, b_f, Wih_b, Whh_b, b_b);

    dim3 gg(1024 / BN, (B_ * S_) / BM);
    k_gemm_in<<<gg, 256>>>();

    k_lstm<<<32, 512>>>();

    k_out<<<(B_ * S_) / 16, 256>>>(Wout, bout);

    k_crf<<<B_, 32>>>(y0, trans, out);
}

// round 4
// speedup vs baseline: 2.1687x; 1.0654x over previous
#include <cuda_runtime.h>
#include <cuda_bf16.h>
#include <cstdint>

#define B_   128
#define S_   512
#define E_   300
#define KP   320     // padded K for GEMM
#define H_   128
#define G4   512     // 4*H
#define T_   12
#define SOS_ 3
#define EOS_ 4
#define NEGV (-10000.0f)

// ---------------- scratch (static device allocations) ----------------
__device__ __align__(16) __nv_bfloat16 g_emb[(size_t)B_*S_*KP];   // [65536][320]
__device__ __align__(16) __nv_bfloat16 g_wcat[1024*KP];           // [1024][320]
__device__ __align__(16) __nv_bfloat16 g_whh[2*G4*H_];            // [2][512][128]
__device__ float g_bias[1024];
__device__ float g_pre[(size_t)2*B_*S_*G4];                       // [2][128][512][512]
__device__ __align__(16) float g_hcat[(size_t)B_*S_*2*H_];        // [65536][256]
__device__ float g_y[(size_t)B_*S_*T_];                           // [65536][12]

// ---------------- helpers ----------------
__device__ __forceinline__ float tanhapx(float x) {
    float r; asm("tanh.approx.f32 %0, %1;" : "=f"(r) : "f"(x)); return r;
}
__device__ __forceinline__ float sigf(float x) {
    return 0.5f + 0.5f * tanhapx(0.5f * x);
}
__device__ __forceinline__ void cp16(void* smem, const void* gmem) {
    uint32_t s = (uint32_t)__cvta_generic_to_shared(smem);
    asm volatile("cp.async.cg.shared.global [%0], [%1], 16;\n" :: "r"(s), "l"(gmem) : "memory");
}
__device__ __forceinline__ void cp_commit() {
    asm volatile("cp.async.commit_group;\n" ::: "memory");
}
template<int N> __device__ __forceinline__ void cp_wait() {
    asm volatile("cp.async.wait_group %0;\n" :: "n"(N) : "memory");
}

// ---------------- K1: embedding gather -> bf16, K-padded ----------------
__global__ void k_prep_emb(const int* __restrict__ x, const float* __restrict__ embed) {
    int row = blockIdx.x;
    int k   = threadIdx.x;
    int xv = x[row];
    float v = (k < E_) ? embed[(size_t)xv * E_ + k] : 0.0f;
    g_emb[(size_t)row * KP + k] = __float2bfloat16(v);
}

// ---------------- K1b: weight packing ----------------
__global__ void k_prep_w(const float* __restrict__ Wih_f, const float* __restrict__ Whh_f,
                         const float* __restrict__ b_f,
                         const float* __restrict__ Wih_b, const float* __restrict__ Whh_b,
                         const float* __restrict__ b_b) {
    int idx = blockIdx.x * blockDim.x + threadIdx.x;
    const int NW = 1024 * KP;
    const int NH = 2 * G4 * H_;
    if (idx < NW) {
        int r = idx / KP, k = idx % KP;
        float v = 0.0f;
        if (k < E_) v = (r < G4) ? Wih_f[r * E_ + k] : Wih_b[(r - G4) * E_ + k];
        g_wcat[idx] = __float2bfloat16(v);
    } else if (idx < NW + NH) {
        int i = idx - NW;
        int d = i / (G4 * H_);
        int rem = i % (G4 * H_);
        float v = d ? Whh_b[rem] : Whh_f[rem];
        g_whh[i] = __float2bfloat16(v);
    } else if (idx < NW + NH + 1024) {
        int n = idx - NW - NH;
        g_bias[n] = (n < G4) ? b_f[n] : b_b[n - G4];
    }
}

// ---------------- K2: input GEMM (bf16 mma.sync, fp32 accum, cp.async 3-stage) ----------------
#define BM 128
#define BN 64
#define BK 32
#define SA 40
#define KITERS (KP / BK)   // 10
#define NSTG 3

__global__ __launch_bounds__(256) void k_gemm_in() {
    __shared__ __align__(16) __nv_bfloat16 As[NSTG][BM * SA];
    __shared__ __align__(16) __nv_bfloat16 Bs[NSTG][BN * SA];
    const int m0 = blockIdx.y * BM;
    const int n0 = blockIdx.x * BN;
    const int tid = threadIdx.x;
    const int warp = tid >> 5, lane = tid & 31;
    const int wm = warp >> 1, wn = warp & 1;

    float acc[2][4][4];
    #pragma unroll
    for (int a = 0; a < 2; a++)
        #pragma unroll
        for (int b = 0; b < 4; b++)
            #pragma unroll
            for (int c = 0; c < 4; c++) acc[a][b][c] = 0.0f;

    const int lr = lane >> 2, lc = (lane & 3) * 2;
    const int ldr = tid >> 2, seg = tid & 3;

    // prologue: stages 0,1
    #pragma unroll
    for (int p = 0; p < 2; p++) {
        const int kt = p * BK;
        cp16(&As[p][ldr * SA + seg * 8],        &g_emb[(size_t)(m0 + ldr) * KP + kt + seg * 8]);
        cp16(&As[p][(ldr + 64) * SA + seg * 8], &g_emb[(size_t)(m0 + ldr + 64) * KP + kt + seg * 8]);
        cp16(&Bs[p][ldr * SA + seg * 8],        &g_wcat[(size_t)(n0 + ldr) * KP + kt + seg * 8]);
        cp_commit();
    }

    for (int it = 0; it < KITERS; it++) {
        if (it + 2 < KITERS) {
            const int kt = (it + 2) * BK;
            const int st = (it + 2) % NSTG;
            cp16(&As[st][ldr * SA + seg * 8],        &g_emb[(size_t)(m0 + ldr) * KP + kt + seg * 8]);
            cp16(&As[st][(ldr + 64) * SA + seg * 8], &g_emb[(size_t)(m0 + ldr + 64) * KP + kt + seg * 8]);
            cp16(&Bs[st][ldr * SA + seg * 8],        &g_wcat[(size_t)(n0 + ldr) * KP + kt + seg * 8]);
            cp_commit();
            cp_wait<2>();
        } else if (it + 1 < KITERS) {
            cp_wait<1>();
        } else {
            cp_wait<0>();
        }
        __syncthreads();
        const int st = it % NSTG;
        #pragma unroll
        for (int ks = 0; ks < 2; ks++) {
            const int kb = ks * 16;
            uint32_t bfr[4][2];
            #pragma unroll
            for (int ni = 0; ni < 4; ni++) {
                int nrow = wn * 32 + ni * 8 + lr;
                bfr[ni][0] = *(const uint32_t*)&Bs[st][nrow * SA + kb + lc];
                bfr[ni][1] = *(const uint32_t*)&Bs[st][nrow * SA + kb + lc + 8];
            }
            #pragma unroll
            for (int mi = 0; mi < 2; mi++) {
                int mrow = wm * 32 + mi * 16;
                uint32_t a0 = *(const uint32_t*)&As[st][(mrow + lr    ) * SA + kb + lc];
                uint32_t a1 = *(const uint32_t*)&As[st][(mrow + lr + 8) * SA + kb + lc];
                uint32_t a2 = *(const uint32_t*)&As[st][(mrow + lr    ) * SA + kb + lc + 8];
                uint32_t a3 = *(const uint32_t*)&As[st][(mrow + lr + 8) * SA + kb + lc + 8];
                #pragma unroll
                for (int ni = 0; ni < 4; ni++) {
                    asm volatile(
                        "mma.sync.aligned.m16n8k16.row.col.f32.bf16.bf16.f32 "
                        "{%0,%1,%2,%3}, {%4,%5,%6,%7}, {%8,%9}, {%0,%1,%2,%3};\n"
                        : "+f"(acc[mi][ni][0]), "+f"(acc[mi][ni][1]),
                          "+f"(acc[mi][ni][2]), "+f"(acc[mi][ni][3])
                        : "r"(a0), "r"(a1), "r"(a2), "r"(a3),
                          "r"(bfr[ni][0]), "r"(bfr[ni][1]));
                }
            }
        }
        __syncthreads();
    }
    // epilogue: add bias, scatter to PRE[d][b][s][j]
    #pragma unroll
    for (int mi = 0; mi < 2; mi++) {
        #pragma unroll
        for (int ni = 0; ni < 4; ni++) {
            int m = m0 + wm * 32 + mi * 16 + lr;
            int n = n0 + wn * 32 + ni * 8 + lc;
            int d = n >> 9, j = n & 511;
            float bias0 = g_bias[n], bias1 = g_bias[n + 1];
            {
                int bb = m >> 9, ss = m & 511;
                size_t base = (((size_t)(d * B_ + bb) * S_ + ss) * G4 + j);
                *(float2*)&g_pre[base] = make_float2(acc[mi][ni][0] + bias0,
                                                     acc[mi][ni][1] + bias1);
            }
            {
                int m2 = m + 8;
                int bb = m2 >> 9, ss = m2 & 511;
                size_t base = (((size_t)(d * B_ + bb) * S_ + ss) * G4 + j);
                *(float2*)&g_pre[base] = make_float2(acc[mi][ni][2] + bias0,
                                                     acc[mi][ni][3] + bias1);
            }
        }
    }
}

// ---------------- K3: tensor-core recurrence ----------------
// 32 blocks = (dir, 8-batch group). 512 threads = 16 warps.
// Warp w: its 4 n8-tiles are gates {w*8 + ni*128} -> i,f,g,o for 2 cells in regs.
// h double-buffered in smem bf16; 1 barrier/step; pf reloaded in-place (no npf).
#define HS 136   // h_sm row stride in bf16 (272B -> conflict-free ldmatrix)

__global__ __launch_bounds__(512, 1) void k_lstm() {
    __shared__ __align__(16) __nv_bfloat16 h_sm[2][16][HS];

    const int d   = blockIdx.x >> 4;
    const int bg  = blockIdx.x & 15;
    const int b0  = bg * 8;
    const int tid = threadIdx.x;
    const int w = tid >> 5, l = tid & 31;
    const int r = l >> 2, cpair = (l & 3) * 2;

    // preload B fragments (Whh) once: 64 regs
    uint32_t Bf[4][8][2];
    #pragma unroll
    for (int ni = 0; ni < 4; ni++) {
        const int n = w * 8 + ni * 128 + r;
        const __nv_bfloat16* src = &g_whh[((size_t)d * G4 + n) * H_ + cpair];
        #pragma unroll
        for (int tk = 0; tk < 8; tk++) {
            Bf[ni][tk][0] = *(const uint32_t*)&src[tk * 16];
            Bf[ni][tk][1] = *(const uint32_t*)&src[tk * 16 + 8];
        }
    }
    // zero both h buffers (rows 8-15 stay zero = M padding)
    for (int i = tid; i < 2 * 16 * HS; i += 512)
        ((__nv_bfloat16*)h_sm)[i] = __float2bfloat16(0.0f);

    const int b  = b0 + r;
    const int m0 = w * 8 + cpair;
    const float* preb = &g_pre[((size_t)(d * B_ + b) * S_) * G4 + m0];
    float* hout = &g_hcat[((size_t)b * S_) * 256 + d * H_ + m0];
    const int sgn = d ? -1 : 1;
    int se = d ? (S_ - 1) : 0;

    float2 pf[4];
    #pragma unroll
    for (int ni = 0; ni < 4; ni++)
        pf[ni] = *(const float2*)&preb[(size_t)se * G4 + ni * 128];

    float cA = 0.0f, cB = 0.0f;
    const uint32_t abase0 =
        (uint32_t)__cvta_generic_to_shared(&h_sm[0][l & 15][(l >> 4) * 8]);

    __syncthreads();

    int buf = 0;
    for (int s = 0; s < S_; s++) {
        // acc init = current pre-activations (bias folded in)
        float acc[4][4];
        #pragma unroll
        for (int ni = 0; ni < 4; ni++) {
            acc[ni][0] = pf[ni].x; acc[ni][1] = pf[ni].y;
            acc[ni][2] = 0.0f;     acc[ni][3] = 0.0f;
        }
        // reload pf for next step (L2-latency hidden under mma phase)
        {
            const int snc = (s < S_ - 1) ? (se + sgn) : se;
            #pragma unroll
            for (int ni = 0; ni < 4; ni++)
                pf[ni] = *(const float2*)&preb[(size_t)snc * G4 + ni * 128];
        }

        const uint32_t abase = abase0 + (uint32_t)buf * (16 * HS * 2);
        #pragma unroll
        for (int tk = 0; tk < 8; tk++) {
            uint32_t a0, a1, a2, a3;
            asm volatile("ldmatrix.sync.aligned.m8n8.x4.shared.b16 {%0,%1,%2,%3}, [%4];\n"
                         : "=r"(a0), "=r"(a1), "=r"(a2), "=r"(a3)
                         : "r"(abase + tk * 32));
            #pragma unroll
            for (int ni = 0; ni < 4; ni++) {
                asm volatile(
                    "mma.sync.aligned.m16n8k16.row.col.f32.bf16.bf16.f32 "
                    "{%0,%1,%2,%3}, {%4,%5,%6,%7}, {%8,%9}, {%0,%1,%2,%3};\n"
                    : "+f"(acc[ni][0]), "+f"(acc[ni][1]),
                      "+f"(acc[ni][2]), "+f"(acc[ni][3])
                    : "r"(a0), "r"(a1), "r"(a2), "r"(a3),
                      "r"(Bf[ni][tk][0]), "r"(Bf[ni][tk][1]));
            }
        }

        // gates: ni 0=i, 1=f, 2=g, 3=o ; 2 cells (m0, m0+1), batch b
        cA = sigf(acc[1][0]) * cA + sigf(acc[0][0]) * tanhapx(acc[2][0]);
        cB = sigf(acc[1][1]) * cB + sigf(acc[0][1]) * tanhapx(acc[2][1]);
        float hA = sigf(acc[3][0]) * tanhapx(cA);
        float hB = sigf(acc[3][1]) * tanhapx(cB);

        *(__nv_bfloat162*)&h_sm[buf ^ 1][r][m0] = __floats2bfloat162_rn(hA, hB);
        *(float2*)&hout[(size_t)se * 256] = make_float2(hA, hB);

        __syncthreads();
        buf ^= 1;
        se += sgn;
    }
}

// ---------------- K4: output linear ----------------
__global__ void k_out(const float* __restrict__ Wout, const float* __restrict__ bout) {
    const int lr = threadIdx.x >> 4;
    const int t  = threadIdx.x & 15;
    const int row = blockIdx.x * 16 + lr;
    if (t >= T_) return;
    float acc = bout[t];
    const float4* hv = (const float4*)&g_hcat[(size_t)row * 256];
    const float4* wv = (const float4*)&Wout[t * 256];
    #pragma unroll 8
    for (int q = 0; q < 64; q++) {
        float4 h4 = hv[q], w4 = wv[q];
        acc += h4.x * w4.x + h4.y * w4.y + h4.z * w4.z + h4.w * w4.w;
    }
    g_y[(size_t)row * T_ + t] = acc;
}

// ---------------- K5: CRF forward + gold ----------------
__global__ void k_crf(const int* __restrict__ y0, const float* __restrict__ trans,
                      float* __restrict__ out) {
    __shared__ float tsm[T_ * T_];
    const int b = blockIdx.x;
    const int lane = threadIdx.x;
    for (int i = lane; i < T_ * T_; i += 32) tsm[i] = trans[i];
    __syncwarp();

    float trow[T_];
    const int irow = (lane < T_) ? lane : 0;
    #pragma unroll
    for (int jj = 0; jj < T_; jj++) trow[jj] = tsm[irow * T_ + jj];

    float score = (lane == SOS_) ? 0.0f : NEGV;
    const float* gyb = &g_y[(size_t)b * S_ * T_];

    float yv_next = (lane < T_) ? gyb[lane] : 0.0f;
    for (int s = 0; s < S_; s++) {
        float yv = yv_next;
        if (s + 1 < S_)
            yv_next = (lane < T_) ? gyb[(s + 1) * T_ + lane] : 0.0f;
        float v[T_];
        float mx = -1e30f;
        #pragma unroll
        for (int jj = 0; jj < T_; jj++) {
            float sj = __shfl_sync(0xffffffffu, score, jj);
            v[jj] = sj + trow[jj];
            mx = fmaxf(mx, v[jj]);
        }
        float sum = 0.0f;
        #pragma unroll
        for (int jj = 0; jj < T_; jj++) sum += __expf(v[jj] - mx);
        score = mx + __logf(sum) + yv;
    }
    float vz = (lane < T_) ? score + tsm[EOS_ * T_ + lane] : -1e30f;
    float mz = vz;
    #pragma unroll
    for (int o = 16; o; o >>= 1) mz = fmaxf(mz, __shfl_xor_sync(0xffffffffu, mz, o));
    float ez = (lane < T_) ? __expf(vz - mz) : 0.0f;
    #pragma unroll
    for (int o = 16; o; o >>= 1) ez += __shfl_xor_sync(0xffffffffu, ez, o);
    float Z = mz + __logf(ez);

    const int* yb = &y0[b * S_];
    float g = 0.0f;
    for (int s = lane; s < S_; s += 32) {
        int cur = yb[s];
        int prev = s ? yb[s - 1] : SOS_;
        g += gyb[s * T_ + cur] + tsm[cur * T_ + prev];
    }
    #pragma unroll
    for (int o = 16; o; o >>= 1) g += __shfl_xor_sync(0xffffffffu, g, o);
    if (lane == 0) {
        g += tsm[EOS_ * T_ + yb[S_ - 1]];
        out[b] = Z - g;
    }
}

// ---------------- launcher ----------------
extern "C" void kernel_launch(void* const* d_in, const int* in_sizes, int n_in,
                              void* d_out, int out_size) {
    const int*   x     = (const int*)d_in[0];
    const int*   y0    = (const int*)d_in[1];
    const float* embed = (const float*)d_in[2];
    const float* Wih_f = (const float*)d_in[3];
    const float* Whh_f = (const float*)d_in[4];
    const float* b_f   = (const float*)d_in[5];
    const float* Wih_b = (const float*)d_in[6];
    const float* Whh_b = (const float*)d_in[7];
    const float* b_b   = (const float*)d_in[8];
    const float* Wout  = (const float*)d_in[9];
    const float* bout  = (const float*)d_in[10];
    const float* trans = (const float*)d_in[11];
    float* out = (float*)d_out;

    k_prep_emb<<<B_ * S_, KP>>>(x, embed);

    const int prep_total = 1024 * KP + 2 * G4 * H_ + 1024;
    k_prep_w<<<(prep_total + 255) / 256, 256>>>(Wih_f, Whh_f, b_f, Wih_b, Whh_b, b_b);

    dim3 gg(1024 / BN, (B_ * S_) / BM);
    k_gemm_in<<<gg, 256>>>();

    k_lstm<<<32, 512>>>();

    k_out<<<(B_ * S_) / 16, 256>>>(Wout, bout);

    k_crf<<<B_, 32>>>(y0, trans, out);
}